// round 13
// baseline (speedup 1.0000x reference)
#include <cuda_runtime.h>
#include <math.h>
#include <stdint.h>

#define BATCH   64
#define NPTS    65536
#define CHUNKS  32
#define CHUNK_ELEMS (NPTS / CHUNKS)   // 2048
#define BDIM    128
#define NWARPS  (BDIM / 32)
#define NVALS   15
#define NITER   (CHUNK_ELEMS / 8 / BDIM)   // 2 iterations, 8 floats/thread/stream

// Per-(batch, chunk) partial sums. Fully overwritten each launch.
__device__ float g_part[BATCH][CHUNKS][NVALS];
// Per-batch arrival counters; last arriving block resets -> graph-replay safe.
__device__ unsigned int g_count[BATCH];

struct f8 { float v[8]; };

// Partial L2 pinning (R11: 26.8->21.0us warm; R12 showed retention is
// capacity-capped ~half of L2). Pin weights+src+tgt.x via evict_last; stream
// tgt.y/tgt.z via evict_first. The streamed (DRAM-bound) loads are
// front-batched before any compute so each thread exposes ~1 DRAM latency
// instead of NITER serialized ones.
__device__ __forceinline__ f8 ldg_last8(const float* p) {
    unsigned long long r0, r1, r2, r3;
    asm volatile("ld.global.nc.L2::evict_last.v4.b64 {%0,%1,%2,%3}, [%4];"
                 : "=l"(r0), "=l"(r1), "=l"(r2), "=l"(r3) : "l"(p));
    f8 r;
    r.v[0] = __uint_as_float((unsigned)(r0));
    r.v[1] = __uint_as_float((unsigned)(r0 >> 32));
    r.v[2] = __uint_as_float((unsigned)(r1));
    r.v[3] = __uint_as_float((unsigned)(r1 >> 32));
    r.v[4] = __uint_as_float((unsigned)(r2));
    r.v[5] = __uint_as_float((unsigned)(r2 >> 32));
    r.v[6] = __uint_as_float((unsigned)(r3));
    r.v[7] = __uint_as_float((unsigned)(r3 >> 32));
    return r;
}

__device__ __forceinline__ f8 ldg_first8(const float* p) {
    unsigned long long r0, r1, r2, r3;
    asm volatile("ld.global.nc.L2::evict_first.v4.b64 {%0,%1,%2,%3}, [%4];"
                 : "=l"(r0), "=l"(r1), "=l"(r2), "=l"(r3) : "l"(p));
    f8 r;
    r.v[0] = __uint_as_float((unsigned)(r0));
    r.v[1] = __uint_as_float((unsigned)(r0 >> 32));
    r.v[2] = __uint_as_float((unsigned)(r1));
    r.v[3] = __uint_as_float((unsigned)(r1 >> 32));
    r.v[4] = __uint_as_float((unsigned)(r2));
    r.v[5] = __uint_as_float((unsigned)(r2 >> 32));
    r.v[6] = __uint_as_float((unsigned)(r3));
    r.v[7] = __uint_as_float((unsigned)(r3 >> 32));
    return r;
}

__device__ __forceinline__ void accum8(float acc[NVALS],
                                       const f8& vw, const f8& vsx, const f8& vsy,
                                       const f8& vsz, const f8& vtx, const f8& vty,
                                       const f8& vtz) {
    #pragma unroll
    for (int e = 0; e < 8; e++) {
        float w  = vw.v[e];
        float sx = vsx.v[e];
        float sy = vsy.v[e];
        float sz = vsz.v[e];
        float tx = vtx.v[e];
        float ty = vty.v[e];
        float tz = vtz.v[e];
        acc[0]  += w * sx;
        acc[1]  += w * sy;
        acc[2]  += w * sz;
        acc[3]  += w * tx;
        acc[4]  += w * ty;
        acc[5]  += w * tz;
        float wsx = w * sx, wsy = w * sy, wsz = w * sz;
        acc[6]  += wsx * tx;
        acc[7]  += wsx * ty;
        acc[8]  += wsx * tz;
        acc[9]  += wsy * tx;
        acc[10] += wsy * ty;
        acc[11] += wsy * tz;
        acc[12] += wsz * tx;
        acc[13] += wsz * ty;
        acc[14] += wsz * tz;
    }
}

// ---------------------------------------------------------------------------
// Per-batch 3x3 weighted-Kabsch solve (fp32 one-sided Jacobi), single thread.
// Rare path (64 executions/launch); __noinline__ keeps regs off the hot loop.
// ---------------------------------------------------------------------------
__device__ __noinline__ void solve_batch(const float vals[NVALS], int b,
                                         float* __restrict__ out) {
    float srcm[3] = { vals[0], vals[1], vals[2] };
    float tgtm[3] = { vals[3], vals[4], vals[5] };

    float a[3][3];   // a[j][i] = H[i][j] (column view)
    #pragma unroll
    for (int i = 0; i < 3; i++)
        #pragma unroll
        for (int j = 0; j < 3; j++)
            a[j][i] = vals[6 + 3 * i + j] - srcm[i] * tgtm[j];

    float V[3][3];
    #pragma unroll
    for (int j = 0; j < 3; j++)
        #pragma unroll
        for (int i = 0; i < 3; i++)
            V[j][i] = (i == j) ? 1.0f : 0.0f;

    #pragma unroll 1
    for (int sweep = 0; sweep < 5; sweep++) {
        #pragma unroll
        for (int p = 0; p < 2; p++) {
            #pragma unroll
            for (int q = p + 1; q < 3; q++) {
                float alpha = a[p][0]*a[p][0] + a[p][1]*a[p][1] + a[p][2]*a[p][2];
                float beta  = a[q][0]*a[q][0] + a[q][1]*a[q][1] + a[q][2]*a[q][2];
                float gamma = a[p][0]*a[q][0] + a[p][1]*a[q][1] + a[p][2]*a[q][2];
                if (gamma * gamma > 1e-24f * alpha * beta + 1e-38f) {
                    float zeta = __fdividef(beta - alpha, 2.0f * gamma);
                    float t = __fdividef(copysignf(1.0f, zeta),
                                         fabsf(zeta) + __fsqrt_rn(1.0f + zeta * zeta));
                    float c = rsqrtf(1.0f + t * t);
                    float s = c * t;
                    #pragma unroll
                    for (int k = 0; k < 3; k++) {
                        float ap = a[p][k], aq = a[q][k];
                        a[p][k] = c * ap - s * aq;
                        a[q][k] = s * ap + c * aq;
                        float vp = V[p][k], vq = V[q][k];
                        V[p][k] = c * vp - s * vq;
                        V[q][k] = s * vp + c * vq;
                    }
                }
            }
        }
    }

    float n2[3];
    #pragma unroll
    for (int j = 0; j < 3; j++)
        n2[j] = a[j][0]*a[j][0] + a[j][1]*a[j][1] + a[j][2]*a[j][2];

    int i0 = 0, i1 = 1, i2 = 2;
    if (n2[i0] < n2[i1]) { int t = i0; i0 = i1; i1 = t; }
    if (n2[i1] < n2[i2]) { int t = i1; i1 = i2; i2 = t; }
    if (n2[i0] < n2[i1]) { int t = i0; i0 = i1; i1 = t; }

    float v1[3], v2[3], v3[3], u1[3], u2[3];
    #pragma unroll
    for (int k = 0; k < 3; k++) {
        v1[k] = V[i0][k]; v2[k] = V[i1][k]; v3[k] = V[i2][k];
        u1[k] = a[i0][k]; u2[k] = a[i1][k];
    }

    {
        float n = rsqrtf(fmaxf(u1[0]*u1[0] + u1[1]*u1[1] + u1[2]*u1[2], 1e-30f));
        #pragma unroll
        for (int k = 0; k < 3; k++) u1[k] *= n;
    }
    {
        float d = u1[0]*u2[0] + u1[1]*u2[1] + u1[2]*u2[2];
        #pragma unroll
        for (int k = 0; k < 3; k++) u2[k] -= d * u1[k];
        float n = rsqrtf(fmaxf(u2[0]*u2[0] + u2[1]*u2[1] + u2[2]*u2[2], 1e-30f));
        #pragma unroll
        for (int k = 0; k < 3; k++) u2[k] *= n;
    }
    float u3[3] = {
        u1[1]*u2[2] - u1[2]*u2[1],
        u1[2]*u2[0] - u1[0]*u2[2],
        u1[0]*u2[1] - u1[1]*u2[0]
    };

    float detV = v1[0]*(v2[1]*v3[2] - v2[2]*v3[1])
               - v2[0]*(v1[1]*v3[2] - v1[2]*v3[1])
               + v3[0]*(v1[1]*v2[2] - v1[2]*v2[1]);

    float R[3][3];
    #pragma unroll
    for (int i = 0; i < 3; i++)
        #pragma unroll
        for (int j = 0; j < 3; j++)
            R[i][j] = v1[i]*u1[j] + v2[i]*u2[j] + detV * v3[i]*u3[j];

    float tvec[3];
    #pragma unroll
    for (int i = 0; i < 3; i++)
        tvec[i] = tgtm[i] - (R[i][0]*srcm[0] + R[i][1]*srcm[1] + R[i][2]*srcm[2]);

    float* Rout = out + (size_t)b * 9;
    float* tout = out + (size_t)BATCH * 9 + (size_t)b * 3;
    #pragma unroll
    for (int i = 0; i < 3; i++)
        #pragma unroll
        for (int j = 0; j < 3; j++)
            Rout[i * 3 + j] = R[i][j];
    #pragma unroll
    for (int i = 0; i < 3; i++) tout[i] = tvec[i];
}

__global__ __launch_bounds__(BDIM)
void svd_fused_kernel(const float* __restrict__ src,
                      const float* __restrict__ tgt,
                      const float* __restrict__ wts,
                      float* __restrict__ out) {
    const int b  = blockIdx.x / CHUNKS;
    const int ch = blockIdx.x % CHUNKS;
    const int base = ch * CHUNK_ELEMS;

    const size_t boff = (size_t)b * 3 * NPTS;
    const float* pw  = wts + (size_t)b * NPTS + base;
    const float* psx = src + boff + 0 * NPTS + base;
    const float* psy = src + boff + 1 * NPTS + base;
    const float* psz = src + boff + 2 * NPTS + base;
    const float* ptx = tgt + boff + 0 * NPTS + base;
    const float* pty = tgt + boff + 1 * NPTS + base;
    const float* ptz = tgt + boff + 2 * NPTS + base;

    // ---- Front-batch ALL DRAM-bound (streamed) loads: 4 x LDG.256 ----
    f8 sty[NITER], stz[NITER];
    #pragma unroll
    for (int k = 0; k < NITER; k++) {
        const int off = (threadIdx.x + k * BDIM) * 8;
        sty[k] = ldg_first8(pty + off);   // streamed: tgt.y
        stz[k] = ldg_first8(ptz + off);   // streamed: tgt.z
    }

    float acc[NVALS];
    #pragma unroll
    for (int v = 0; v < NVALS; v++) acc[v] = 0.0f;

    // Pinned (L2-hit) loads + compute run while the misses are in flight.
    #pragma unroll
    for (int k = 0; k < NITER; k++) {
        const int off = (threadIdx.x + k * BDIM) * 8;
        f8 vw  = ldg_last8(pw  + off);   // pinned: weights
        f8 vsx = ldg_last8(psx + off);   // pinned: src
        f8 vsy = ldg_last8(psy + off);
        f8 vsz = ldg_last8(psz + off);
        f8 vtx = ldg_last8(ptx + off);   // pinned: tgt.x
        accum8(acc, vw, vsx, vsy, vsz, vtx, sty[k], stz[k]);
    }

    // warp reduce
    #pragma unroll
    for (int v = 0; v < NVALS; v++) {
        #pragma unroll
        for (int off = 16; off > 0; off >>= 1)
            acc[v] += __shfl_down_sync(0xFFFFFFFFu, acc[v], off);
    }

    __shared__ float smem[NVALS][NWARPS];
    const int warp = threadIdx.x >> 5;
    const int lane = threadIdx.x & 31;
    if (lane == 0) {
        #pragma unroll
        for (int v = 0; v < NVALS; v++) smem[v][warp] = acc[v];
    }
    __syncthreads();

    if (threadIdx.x < NVALS) {
        float s = 0.0f;
        #pragma unroll
        for (int k = 0; k < NWARPS; k++) s += smem[threadIdx.x][k];
        g_part[b][ch][threadIdx.x] = s;
    }

    // --- last-block-done: the final arriving block for this batch solves ---
    __shared__ int s_last;
    __threadfence();  // release: g_part writes visible device-wide
    if (threadIdx.x == 0) {
        unsigned int old = atomicAdd(&g_count[b], 1u);
        s_last = (old == CHUNKS - 1) ? 1 : 0;
        if (s_last) g_count[b] = 0;  // reset for next graph replay
    }
    __syncthreads();
    if (!s_last) return;

    if (warp == 0) {
        __threadfence();  // acquire side
        float vals[NVALS];
        #pragma unroll
        for (int v = 0; v < NVALS; v++)
            vals[v] = (lane < CHUNKS) ? g_part[b][lane][v] : 0.0f;
        #pragma unroll
        for (int v = 0; v < NVALS; v++) {
            #pragma unroll
            for (int off = CHUNKS / 2; off > 0; off >>= 1)
                vals[v] += __shfl_down_sync(0xFFFFFFFFu, vals[v], off);
        }
        if (lane == 0) solve_batch(vals, b, out);
    }
}

extern "C" void kernel_launch(void* const* d_in, const int* in_sizes, int n_in,
                              void* d_out, int out_size) {
    const float* src = (const float*)d_in[0];
    const float* tgt = (const float*)d_in[1];
    const float* wts = (const float*)d_in[2];
    float* out = (float*)d_out;

    svd_fused_kernel<<<BATCH * CHUNKS, BDIM>>>(src, tgt, wts, out);
}

// round 14
// speedup vs baseline: 1.2145x; 1.2145x over previous
#include <cuda_runtime.h>
#include <math.h>
#include <stdint.h>

#define BATCH   64
#define NPTS    65536
#define CHUNKS  16
#define CHUNK_ELEMS (NPTS / CHUNKS)   // 4096
#define BDIM    128
#define NWARPS  (BDIM / 32)
#define NVALS   15
#define NITER   (CHUNK_ELEMS / 4 / BDIM)   // 8 iterations per thread

// Per-(batch, chunk) partial sums. Fully overwritten each launch.
__device__ float g_part[BATCH][CHUNKS][NVALS];
// Per-batch arrival counters; last arriving block resets -> graph-replay safe.
__device__ unsigned int g_count[BATCH];

// L2 eviction policies via createpolicy + cache_hint: unlike the bare
// .L2::evict_last modifier (which ptxas only accepts on 32B vectors),
// the cache_hint form works with ordinary 16B .v4.f32 loads -> half the
// destination register pressure, higher occupancy, same retention win
// (R11: pin 67MB -> 26.8->21.0us warm).
__device__ __forceinline__ uint64_t make_policy_last() {
    uint64_t pol;
    asm("createpolicy.fractional.L2::evict_last.b64 %0, 1.0;" : "=l"(pol));
    return pol;
}
__device__ __forceinline__ uint64_t make_policy_first() {
    uint64_t pol;
    asm("createpolicy.fractional.L2::evict_first.b64 %0, 1.0;" : "=l"(pol));
    return pol;
}

__device__ __forceinline__ float4 ldg_hint(const float4* p, uint64_t pol) {
    float4 v;
    asm volatile("ld.global.nc.L2::cache_hint.v4.f32 {%0,%1,%2,%3}, [%4], %5;"
                 : "=f"(v.x), "=f"(v.y), "=f"(v.z), "=f"(v.w)
                 : "l"(p), "l"(pol));
    return v;
}

__device__ __forceinline__ void accum7(float acc[NVALS], const float4 v[7]) {
    // v: 0=w 1=sx 2=sy 3=sz 4=tx 5=ty 6=tz
    #pragma unroll
    for (int e = 0; e < 4; e++) {
        float w  = ((const float*)&v[0])[e];
        float sx = ((const float*)&v[1])[e];
        float sy = ((const float*)&v[2])[e];
        float sz = ((const float*)&v[3])[e];
        float tx = ((const float*)&v[4])[e];
        float ty = ((const float*)&v[5])[e];
        float tz = ((const float*)&v[6])[e];
        acc[0]  += w * sx;
        acc[1]  += w * sy;
        acc[2]  += w * sz;
        acc[3]  += w * tx;
        acc[4]  += w * ty;
        acc[5]  += w * tz;
        float wsx = w * sx, wsy = w * sy, wsz = w * sz;
        acc[6]  += wsx * tx;
        acc[7]  += wsx * ty;
        acc[8]  += wsx * tz;
        acc[9]  += wsy * tx;
        acc[10] += wsy * ty;
        acc[11] += wsy * tz;
        acc[12] += wsz * tx;
        acc[13] += wsz * ty;
        acc[14] += wsz * tz;
    }
}

// ---------------------------------------------------------------------------
// Per-batch 3x3 weighted-Kabsch solve (fp32 one-sided Jacobi), single thread.
// Rare path (64 executions/launch); __noinline__ keeps regs off the hot loop.
// ---------------------------------------------------------------------------
__device__ __noinline__ void solve_batch(const float vals[NVALS], int b,
                                         float* __restrict__ out) {
    float srcm[3] = { vals[0], vals[1], vals[2] };
    float tgtm[3] = { vals[3], vals[4], vals[5] };

    float a[3][3];   // a[j][i] = H[i][j] (column view)
    #pragma unroll
    for (int i = 0; i < 3; i++)
        #pragma unroll
        for (int j = 0; j < 3; j++)
            a[j][i] = vals[6 + 3 * i + j] - srcm[i] * tgtm[j];

    float V[3][3];
    #pragma unroll
    for (int j = 0; j < 3; j++)
        #pragma unroll
        for (int i = 0; i < 3; i++)
            V[j][i] = (i == j) ? 1.0f : 0.0f;

    #pragma unroll 1
    for (int sweep = 0; sweep < 5; sweep++) {
        #pragma unroll
        for (int p = 0; p < 2; p++) {
            #pragma unroll
            for (int q = p + 1; q < 3; q++) {
                float alpha = a[p][0]*a[p][0] + a[p][1]*a[p][1] + a[p][2]*a[p][2];
                float beta  = a[q][0]*a[q][0] + a[q][1]*a[q][1] + a[q][2]*a[q][2];
                float gamma = a[p][0]*a[q][0] + a[p][1]*a[q][1] + a[p][2]*a[q][2];
                if (gamma * gamma > 1e-24f * alpha * beta + 1e-38f) {
                    float zeta = __fdividef(beta - alpha, 2.0f * gamma);
                    float t = __fdividef(copysignf(1.0f, zeta),
                                         fabsf(zeta) + __fsqrt_rn(1.0f + zeta * zeta));
                    float c = rsqrtf(1.0f + t * t);
                    float s = c * t;
                    #pragma unroll
                    for (int k = 0; k < 3; k++) {
                        float ap = a[p][k], aq = a[q][k];
                        a[p][k] = c * ap - s * aq;
                        a[q][k] = s * ap + c * aq;
                        float vp = V[p][k], vq = V[q][k];
                        V[p][k] = c * vp - s * vq;
                        V[q][k] = s * vp + c * vq;
                    }
                }
            }
        }
    }

    float n2[3];
    #pragma unroll
    for (int j = 0; j < 3; j++)
        n2[j] = a[j][0]*a[j][0] + a[j][1]*a[j][1] + a[j][2]*a[j][2];

    int i0 = 0, i1 = 1, i2 = 2;
    if (n2[i0] < n2[i1]) { int t = i0; i0 = i1; i1 = t; }
    if (n2[i1] < n2[i2]) { int t = i1; i1 = i2; i2 = t; }
    if (n2[i0] < n2[i1]) { int t = i0; i0 = i1; i1 = t; }

    float v1[3], v2[3], v3[3], u1[3], u2[3];
    #pragma unroll
    for (int k = 0; k < 3; k++) {
        v1[k] = V[i0][k]; v2[k] = V[i1][k]; v3[k] = V[i2][k];
        u1[k] = a[i0][k]; u2[k] = a[i1][k];
    }

    {
        float n = rsqrtf(fmaxf(u1[0]*u1[0] + u1[1]*u1[1] + u1[2]*u1[2], 1e-30f));
        #pragma unroll
        for (int k = 0; k < 3; k++) u1[k] *= n;
    }
    {
        float d = u1[0]*u2[0] + u1[1]*u2[1] + u1[2]*u2[2];
        #pragma unroll
        for (int k = 0; k < 3; k++) u2[k] -= d * u1[k];
        float n = rsqrtf(fmaxf(u2[0]*u2[0] + u2[1]*u2[1] + u2[2]*u2[2], 1e-30f));
        #pragma unroll
        for (int k = 0; k < 3; k++) u2[k] *= n;
    }
    float u3[3] = {
        u1[1]*u2[2] - u1[2]*u2[1],
        u1[2]*u2[0] - u1[0]*u2[2],
        u1[0]*u2[1] - u1[1]*u2[0]
    };

    float detV = v1[0]*(v2[1]*v3[2] - v2[2]*v3[1])
               - v2[0]*(v1[1]*v3[2] - v1[2]*v3[1])
               + v3[0]*(v1[1]*v2[2] - v1[2]*v2[1]);

    float R[3][3];
    #pragma unroll
    for (int i = 0; i < 3; i++)
        #pragma unroll
        for (int j = 0; j < 3; j++)
            R[i][j] = v1[i]*u1[j] + v2[i]*u2[j] + detV * v3[i]*u3[j];

    float tvec[3];
    #pragma unroll
    for (int i = 0; i < 3; i++)
        tvec[i] = tgtm[i] - (R[i][0]*srcm[0] + R[i][1]*srcm[1] + R[i][2]*srcm[2]);

    float* Rout = out + (size_t)b * 9;
    float* tout = out + (size_t)BATCH * 9 + (size_t)b * 3;
    #pragma unroll
    for (int i = 0; i < 3; i++)
        #pragma unroll
        for (int j = 0; j < 3; j++)
            Rout[i * 3 + j] = R[i][j];
    #pragma unroll
    for (int i = 0; i < 3; i++) tout[i] = tvec[i];
}

__global__ __launch_bounds__(BDIM)
void svd_fused_kernel(const float* __restrict__ src,
                      const float* __restrict__ tgt,
                      const float* __restrict__ wts,
                      float* __restrict__ out) {
    const int b  = blockIdx.x / CHUNKS;
    const int ch = blockIdx.x % CHUNKS;
    const int base = ch * CHUNK_ELEMS;

    const size_t boff = (size_t)b * 3 * NPTS;
    const float4* p[7];
    p[0] = (const float4*)(wts + (size_t)b * NPTS + base);        // pinned
    p[1] = (const float4*)(src + boff + 0 * NPTS + base);         // pinned
    p[2] = (const float4*)(src + boff + 1 * NPTS + base);         // pinned
    p[3] = (const float4*)(src + boff + 2 * NPTS + base);         // pinned
    p[4] = (const float4*)(tgt + boff + 0 * NPTS + base);         // pinned
    p[5] = (const float4*)(tgt + boff + 1 * NPTS + base);         // streamed
    p[6] = (const float4*)(tgt + boff + 2 * NPTS + base);         // streamed

    const uint64_t pol_last  = make_policy_last();
    const uint64_t pol_first = make_policy_first();
    uint64_t pol[7] = { pol_last, pol_last, pol_last, pol_last,
                        pol_last, pol_first, pol_first };

    float acc[NVALS];
    #pragma unroll
    for (int v = 0; v < NVALS; v++) acc[v] = 0.0f;

    // Depth-2 software pipeline (R7 structure, regs ~66 -> high occupancy):
    // iteration k+1's 7 LDG.128s in flight while iteration k's FMAs retire.
    float4 cur[7], nxt[7];
    #pragma unroll
    for (int s = 0; s < 7; s++) cur[s] = ldg_hint(p[s] + threadIdx.x, pol[s]);

    #pragma unroll
    for (int k = 0; k < NITER - 1; k++) {
        const int inext = threadIdx.x + (k + 1) * BDIM;
        #pragma unroll
        for (int s = 0; s < 7; s++) nxt[s] = ldg_hint(p[s] + inext, pol[s]);
        accum7(acc, cur);
        #pragma unroll
        for (int s = 0; s < 7; s++) cur[s] = nxt[s];
    }
    accum7(acc, cur);

    // warp reduce
    #pragma unroll
    for (int v = 0; v < NVALS; v++) {
        #pragma unroll
        for (int off = 16; off > 0; off >>= 1)
            acc[v] += __shfl_down_sync(0xFFFFFFFFu, acc[v], off);
    }

    __shared__ float smem[NVALS][NWARPS];
    const int warp = threadIdx.x >> 5;
    const int lane = threadIdx.x & 31;
    if (lane == 0) {
        #pragma unroll
        for (int v = 0; v < NVALS; v++) smem[v][warp] = acc[v];
    }
    __syncthreads();

    if (threadIdx.x < NVALS) {
        float s = 0.0f;
        #pragma unroll
        for (int k = 0; k < NWARPS; k++) s += smem[threadIdx.x][k];
        g_part[b][ch][threadIdx.x] = s;
    }

    // --- last-block-done: the final arriving block for this batch solves ---
    __shared__ int s_last;
    __threadfence();  // release: g_part writes visible device-wide
    if (threadIdx.x == 0) {
        unsigned int old = atomicAdd(&g_count[b], 1u);
        s_last = (old == CHUNKS - 1) ? 1 : 0;
        if (s_last) g_count[b] = 0;  // reset for next graph replay
    }
    __syncthreads();
    if (!s_last) return;

    if (warp == 0) {
        __threadfence();  // acquire side
        float vals[NVALS];
        #pragma unroll
        for (int v = 0; v < NVALS; v++)
            vals[v] = (lane < CHUNKS) ? g_part[b][lane][v] : 0.0f;
        #pragma unroll
        for (int v = 0; v < NVALS; v++) {
            #pragma unroll
            for (int off = CHUNKS / 2; off > 0; off >>= 1)
                vals[v] += __shfl_down_sync(0xFFFFFFFFu, vals[v], off);
        }
        if (lane == 0) solve_batch(vals, b, out);
    }
}

extern "C" void kernel_launch(void* const* d_in, const int* in_sizes, int n_in,
                              void* d_out, int out_size) {
    const float* src = (const float*)d_in[0];
    const float* tgt = (const float*)d_in[1];
    const float* wts = (const float*)d_in[2];
    float* out = (float*)d_out;

    svd_fused_kernel<<<BATCH * CHUNKS, BDIM>>>(src, tgt, wts, out);
}